// round 6
// baseline (speedup 1.0000x reference)
#include <cuda_runtime.h>
#include <math.h>

// ClusteredAttention: b=4, l=4096, d=64 fp32, labels in [0,8).
// Counting-sort tokens by label -> perm/slab/block-table. Main kernel reads
// Q/K/V directly through perm (no gather pass), uses cluster-aligned 64-query
// blocks with 8x4 register tiles (128 threads), and absorbs the time-query
// split-softmax partials into its spare grid slots. Tiny combine kernel last.

#define LSEQ 4096
#define LM1  4095
#define HD   64
#define BM   64
#define BN   64
#define PAD  65
#define MAXB 4
#define MAXBLK 72
#define TQ_CHUNKS 128
#define TQ_NCH    (LSEQ / TQ_CHUNKS)   // 32
#define GRIDX     (MAXBLK + TQ_NCH)    // 104

__device__ int   g_perm[MAXB * LSEQ];   // sorted pos -> original index
__device__ int   g_slab[MAXB * LSEQ];   // sorted labels; pos LM1 = -2 sentinel
__device__ int4  g_btab[MAXB * MAXBLK]; // per block: {q0, qe, kb, ke}
__device__ int   g_nblk[MAXB];
__device__ float g_tq[MAXB * TQ_NCH * (HD + 2)];

// ---------------------------------------------------------------------------
// Kernel A: stable counting sort by label + cluster-aligned block table.
// ---------------------------------------------------------------------------
__global__ void sort_kernel(const int* __restrict__ lab32)
{
    __shared__ int cnt[8][256];
    __shared__ int ex[8][256];
    __shared__ int tot[8];
    __shared__ int segstart[8];
    __shared__ int sh_is64;

    const int b = blockIdx.x;
    const int tid = threadIdx.x;

    if (tid == 0) {
        int f = 1;
        #pragma unroll
        for (int k = 0; k < 32; k++)
            if (lab32[2 * k + 1] != 0) { f = 0; break; }
        sh_is64 = f;
    }
    __syncthreads();
    const int is64 = sh_is64;
    const int labbase = b * LM1;

    int mylab[16];
    int lh[8] = {0, 0, 0, 0, 0, 0, 0, 0};
    #pragma unroll
    for (int k = 0; k < 16; k++) {
        int i = tid * 16 + k;
        int l = -1;
        if (i < LM1) {
            int gi = labbase + i;
            l = lab32[is64 ? (2 * gi) : gi];
            lh[l]++;
        }
        mylab[k] = l;
    }
    #pragma unroll
    for (int l = 0; l < 8; l++) cnt[l][tid] = lh[l];
    __syncthreads();

    {
        int w = tid >> 5, lane = tid & 31;
        int carry = 0;
        for (int c = 0; c < 8; c++) {
            int t = c * 32 + lane;
            int v = cnt[w][t];
            int x = v;
            #pragma unroll
            for (int o = 1; o < 32; o <<= 1) {
                int y = __shfl_up_sync(0xffffffffu, x, o);
                if (lane >= o) x += y;
            }
            ex[w][t] = carry + x - v;
            carry += __shfl_sync(0xffffffffu, x, 31);
        }
        if (lane == 0) tot[w] = carry;
    }
    __syncthreads();

    if (tid == 0) {
        int s = 0;
        int nb = 0;
        #pragma unroll
        for (int l = 0; l < 8; l++) {
            segstart[l] = s;
            int e = s + tot[l];
            int kb = s & ~(BN - 1);
            int ke = min((e + BN - 1) & ~(BN - 1), LSEQ);
            for (int q0 = s; q0 < e; q0 += BM) {
                g_btab[b * MAXBLK + nb] = make_int4(q0, e, kb, ke);
                nb++;
            }
            s = e;
        }
        g_nblk[b] = nb;
        g_perm[b * LSEQ + LM1] = LM1;
        g_slab[b * LSEQ + LM1] = -2;
    }
    __syncthreads();

    int run[8] = {0, 0, 0, 0, 0, 0, 0, 0};
    #pragma unroll
    for (int k = 0; k < 16; k++) {
        int l = mylab[k];
        if (l >= 0) {
            int pos = segstart[l] + ex[l][tid] + run[l]++;
            int i = tid * 16 + k;
            g_perm[b * LSEQ + pos] = i;
            g_slab[b * LSEQ + pos] = l;
        }
    }
}

// ---------------------------------------------------------------------------
// Kernel B: main kernel. 128 threads.
//   slot <  nblk          : block-sparse flash attention (8x4 reg tiles)
//   nblk <= slot < nblk+32: one time-query split-softmax chunk
// ---------------------------------------------------------------------------
__global__ __launch_bounds__(128)
void clustered_attn_kernel(const float* __restrict__ Q,
                           const float* __restrict__ K,
                           const float* __restrict__ V,
                           float* __restrict__ Out)
{
    extern __shared__ float sm[];

    const int b    = blockIdx.y;
    const int slot = blockIdx.x;
    const int tid  = threadIdx.x;
    const int nblk = g_nblk[b];
    const long long bbase = (long long)b * LSEQ;
    const float scale = 0.125f;

    // ===================== time-query chunk path =====================
    if (slot >= nblk) {
        const int c = slot - nblk;
        if (c >= TQ_NCH) return;

        float* q    = sm;            // [64]
        float* p    = sm + 64;       // [128]
        float* red  = sm + 192;      // [8] used
        float* vacc = sm + 256;      // [2][64]

        if (tid < HD) q[tid] = Q[(bbase + LM1) * HD + tid];
        __syncthreads();

        const int j = c * TQ_CHUNKS + tid;
        const float* kr = K + (bbase + j) * HD;
        float dot = 0.0f;
        #pragma unroll
        for (int d = 0; d < HD; d += 4) {
            float4 k4 = *reinterpret_cast<const float4*>(kr + d);
            dot += q[d] * k4.x + q[d + 1] * k4.y + q[d + 2] * k4.z + q[d + 3] * k4.w;
        }
        dot *= scale;

        float m = dot;
        #pragma unroll
        for (int o = 16; o >= 1; o >>= 1)
            m = fmaxf(m, __shfl_xor_sync(0xffffffffu, m, o));
        if ((tid & 31) == 0) red[tid >> 5] = m;
        __syncthreads();
        m = fmaxf(fmaxf(red[0], red[1]), fmaxf(red[2], red[3]));

        float pv = __expf(dot - m);
        p[tid] = pv;

        float s = pv;
        #pragma unroll
        for (int o = 16; o >= 1; o >>= 1)
            s += __shfl_xor_sync(0xffffffffu, s, o);
        if ((tid & 31) == 0) red[4 + (tid >> 5)] = s;
        __syncthreads();
        s = red[4] + red[5] + red[6] + red[7];

        const int d = tid & 63, h = tid >> 6;
        float a = 0.0f;
        #pragma unroll 8
        for (int jj = h * 64; jj < h * 64 + 64; jj++)
            a += p[jj] * V[(bbase + c * TQ_CHUNKS + jj) * HD + d];
        vacc[h * HD + d] = a;
        __syncthreads();

        float* out = g_tq + (b * TQ_NCH + c) * (HD + 2);
        if (tid < HD) out[tid] = vacc[tid] + vacc[HD + tid];
        else if (tid == HD) { out[HD] = m; out[HD + 1] = s; }
        return;
    }

    // ===================== attention path =====================
    float* Qt = sm;                       // [HD][PAD]  Qt[d*PAD + m]
    float* Kt = Qt + HD * PAD;            // [HD][PAD]  Kt[d*PAD + n]
    float* Pt = Kt + HD * PAD;            // [BN][PAD]  Pt[n*PAD + m]
    float* Vs = Pt + BN * PAD;            // [BN][HD]
    int*   klabs = (int*)(Vs + BN * HD);  // [BN]
    float* kt = (float*)(klabs + BN);     // [HD] time key
    float* vt = kt + HD;                  // [HD] time value

    const int4 blk = g_btab[b * MAXBLK + slot];
    const int q0 = blk.x, qe = blk.y, kb = blk.z, ke = blk.w;

    const int tx = tid & 15;              // 4 key cols: 4*tx+j
    const int ty = tid >> 4;              // 8 query rows: 8*ty+i
    const int* perm = g_perm + b * LSEQ;
    const int* slab = g_slab + b * LSEQ;

    // ---- prologue: Q tile transposed via perm (2 threads per row, float4)
    {
        int r = tid >> 1, h = tid & 1;
        int rr = min(q0 + r, LM1);
        int src = perm[rr];
        const float4* qrow = reinterpret_cast<const float4*>(Q + (bbase + src) * HD) + h * 8;
        #pragma unroll
        for (int k2 = 0; k2 < 8; k2++) {
            float4 v4 = qrow[k2];
            int d = h * 32 + k2 * 4;
            Qt[(d + 0) * PAD + r] = v4.x;
            Qt[(d + 1) * PAD + r] = v4.y;
            Qt[(d + 2) * PAD + r] = v4.z;
            Qt[(d + 3) * PAD + r] = v4.w;
        }
    }
    if (tid < HD) kt[tid] = K[(bbase + LM1) * HD + tid];
    else          vt[tid - HD] = V[(bbase + LM1) * HD + (tid - HD)];

    int qlab[8];
    #pragma unroll
    for (int i = 0; i < 8; i++) {
        int r = q0 + ty * 8 + i;
        qlab[i] = (r < qe) ? slab[r] : -3;   // -3 matches nothing
    }

    float mrow[8], lrow[8], acc[8][4];
    #pragma unroll
    for (int i = 0; i < 8; i++) {
        mrow[i] = -INFINITY;
        lrow[i] = 0.0f;
        #pragma unroll
        for (int j = 0; j < 4; j++) acc[i][j] = 0.0f;
    }

    for (int n0 = kb; n0 < ke; n0 += BN) {
        __syncthreads();   // prev compute done (also orders prologue writes)

        // ---- load K (transposed) + V tiles through perm
        {
            int r = tid >> 1, h = tid & 1;
            int src = perm[n0 + r];
            const float4* krow = reinterpret_cast<const float4*>(K + (bbase + src) * HD) + h * 8;
            const float4* vrow = reinterpret_cast<const float4*>(V + (bbase + src) * HD) + h * 8;
            #pragma unroll
            for (int k2 = 0; k2 < 8; k2++) {
                float4 k4 = krow[k2];
                int d = h * 32 + k2 * 4;
                Kt[(d + 0) * PAD + r] = k4.x;
                Kt[(d + 1) * PAD + r] = k4.y;
                Kt[(d + 2) * PAD + r] = k4.z;
                Kt[(d + 3) * PAD + r] = k4.w;
                float4 v4 = vrow[k2];
                *reinterpret_cast<float4*>(&Vs[r * HD + d]) = v4;
            }
            if (tid < BN) klabs[tid] = slab[n0 + tid];
        }
        __syncthreads();

        // ---- S = Q K^T : 8x4 per thread
        float s[8][4];
        #pragma unroll
        for (int i = 0; i < 8; i++)
            #pragma unroll
            for (int j = 0; j < 4; j++) s[i][j] = 0.0f;

        #pragma unroll 4
        for (int d = 0; d < HD; d++) {
            float a[8], bb[4];
            #pragma unroll
            for (int i = 0; i < 8; i++) a[i]  = Qt[d * PAD + 8 * ty + i];
            #pragma unroll
            for (int j = 0; j < 4; j++) bb[j] = Kt[d * PAD + 4 * tx + j];
            #pragma unroll
            for (int i = 0; i < 8; i++)
                #pragma unroll
                for (int j = 0; j < 4; j++) s[i][j] += a[i] * bb[j];
        }

        int klj[4];
        #pragma unroll
        for (int j = 0; j < 4; j++) klj[j] = klabs[4 * tx + j];

        #pragma unroll
        for (int i = 0; i < 8; i++)
            #pragma unroll
            for (int j = 0; j < 4; j++)
                s[i][j] = (qlab[i] == klj[j]) ? s[i][j] * scale : -INFINITY;

        // ---- online softmax (16-lane row groups; xor 8..1 stays in group)
        #pragma unroll
        for (int i = 0; i < 8; i++) {
            float tm = fmaxf(fmaxf(s[i][0], s[i][1]), fmaxf(s[i][2], s[i][3]));
            #pragma unroll
            for (int o = 8; o >= 1; o >>= 1)
                tm = fmaxf(tm, __shfl_xor_sync(0xffffffffu, tm, o));

            float newm = fmaxf(mrow[i], tm);
            float mref = (newm == -INFINITY) ? 0.0f : newm;
            float f = __expf(mrow[i] - mref);

            float rs = 0.0f;
            #pragma unroll
            for (int j = 0; j < 4; j++) {
                float p = __expf(s[i][j] - mref);
                s[i][j] = p;
                rs += p;
            }
            #pragma unroll
            for (int o = 8; o >= 1; o >>= 1)
                rs += __shfl_xor_sync(0xffffffffu, rs, o);

            lrow[i] = lrow[i] * f + rs;
            mrow[i] = newm;
            #pragma unroll
            for (int j = 0; j < 4; j++) acc[i][j] *= f;
        }

        // ---- stage P^T, then O += P @ V
        #pragma unroll
        for (int i = 0; i < 8; i++)
            #pragma unroll
            for (int j = 0; j < 4; j++)
                Pt[(4 * tx + j) * PAD + (8 * ty + i)] = s[i][j];
        __syncthreads();

        #pragma unroll 4
        for (int n = 0; n < BN; n++) {
            float a[8];
            #pragma unroll
            for (int i = 0; i < 8; i++) a[i] = Pt[n * PAD + 8 * ty + i];
            float4 bv = *reinterpret_cast<const float4*>(&Vs[n * HD + 4 * tx]);
            #pragma unroll
            for (int i = 0; i < 8; i++) {
                acc[i][0] += a[i] * bv.x;
                acc[i][1] += a[i] * bv.y;
                acc[i][2] += a[i] * bv.z;
                acc[i][3] += a[i] * bv.w;
            }
        }
    }

    // ---- time key column (every real query attends to it)
    #pragma unroll
    for (int i = 0; i < 8; i++) {
        float part = 0.0f;
        #pragma unroll
        for (int jj = 0; jj < 4; jj++)
            part += Qt[(4 * tx + jj) * PAD + (8 * ty + i)] * kt[4 * tx + jj];
        #pragma unroll
        for (int o = 8; o >= 1; o >>= 1)
            part += __shfl_xor_sync(0xffffffffu, part, o);
        float st = part * scale;

        float newm = fmaxf(mrow[i], st);
        float f = __expf(mrow[i] - newm);
        float p = __expf(st - newm);
        lrow[i] = lrow[i] * f + p;
        mrow[i] = newm;
        #pragma unroll
        for (int j = 0; j < 4; j++)
            acc[i][j] = acc[i][j] * f + p * vt[4 * tx + j];
    }

    // ---- epilogue: normalize + scatter (only rows owned by this block)
    #pragma unroll
    for (int i = 0; i < 8; i++) {
        int r = q0 + 8 * ty + i;
        if (r < qe) {
            float inv = 1.0f / lrow[i];
            int orig = perm[r];
            float4 o4;
            o4.x = acc[i][0] * inv;
            o4.y = acc[i][1] * inv;
            o4.z = acc[i][2] * inv;
            o4.w = acc[i][3] * inv;
            *reinterpret_cast<float4*>(&Out[(bbase + orig) * HD + 4 * tx]) = o4;
        }
    }
}

// ---------------------------------------------------------------------------
// Kernel C: combine time-query partials. Grid = B, 64 threads.
// ---------------------------------------------------------------------------
__global__ void timeq_combine(float* __restrict__ Out)
{
    const int b = blockIdx.x;
    const int tid = threadIdx.x;
    const float* part = g_tq + b * TQ_NCH * (HD + 2);

    float M = -INFINITY;
    #pragma unroll
    for (int c = 0; c < TQ_NCH; c++)
        M = fmaxf(M, part[c * (HD + 2) + HD]);

    float stot = 0.0f, a = 0.0f;
    #pragma unroll
    for (int c = 0; c < TQ_NCH; c++) {
        float f = __expf(part[c * (HD + 2) + HD] - M);
        stot += part[c * (HD + 2) + HD + 1] * f;
        a    += part[c * (HD + 2) + tid] * f;
    }
    Out[((long long)b * LSEQ + LM1) * HD + tid] = a / stot;
}

// ---------------------------------------------------------------------------
extern "C" void kernel_launch(void* const* d_in, const int* in_sizes, int n_in,
                              void* d_out, int out_size)
{
    const float* Q = (const float*)d_in[0];
    const float* K = (const float*)d_in[1];
    const float* V = (const float*)d_in[2];
    const int* lab = (const int*)d_in[3];
    float* Out = (float*)d_out;

    const int B = in_sizes[0] / (LSEQ * HD);

    sort_kernel<<<B, 256>>>(lab);

    const int smem_bytes = (HD * PAD * 2 + BN * PAD + BN * HD + 2 * HD) * (int)sizeof(float)
                           + BN * (int)sizeof(int);
    cudaFuncSetAttribute(clustered_attn_kernel,
                         cudaFuncAttributeMaxDynamicSharedMemorySize, smem_bytes);
    dim3 grid(GRIDX, B);
    clustered_attn_kernel<<<grid, 128, smem_bytes>>>(Q, K, V, Out);

    timeq_combine<<<B, HD>>>(Out);
}

// round 7
// speedup vs baseline: 1.4272x; 1.4272x over previous
#include <cuda_runtime.h>
#include <math.h>

// ClusteredAttention: b=4, l=4096, d=64 fp32, labels in [0,8).
// Counting-sort by label -> perm/slab/block-table; gather K/V cluster-
// contiguous; flash-attend cluster-aligned 64-query blocks (256 thr, 4x4
// register tiles = round-5 proven config; Q gathered in-kernel via perm).
// Time-query split-softmax chunks absorbed into spare grid slots; tiny
// combine kernel last.

#define LSEQ 4096
#define LM1  4095
#define HD   64
#define BM   64
#define BN   64
#define PAD  65
#define NTHREADS 256
#define MAXB 4
#define MAXBLK 72
#define TQ_CHUNKS 256
#define TQ_NCH    (LSEQ / TQ_CHUNKS)   // 16
#define GRIDX     (MAXBLK + TQ_NCH)    // 88

__device__ float g_Ks[MAXB * LSEQ * HD];
__device__ float g_Vs[MAXB * LSEQ * HD];
__device__ int   g_perm[MAXB * LSEQ];   // sorted pos -> original index
__device__ int   g_slab[MAXB * LSEQ];   // sorted labels; pos LM1 = -2 sentinel
__device__ int4  g_btab[MAXB * MAXBLK]; // per block: {q0, qe, kb, ke}
__device__ int   g_nblk[MAXB];
__device__ float g_tq[MAXB * TQ_NCH * (HD + 2)];

// ---------------------------------------------------------------------------
// Kernel A: stable counting sort by label + cluster-aligned block table.
// ---------------------------------------------------------------------------
__global__ void sort_kernel(const int* __restrict__ lab32)
{
    __shared__ int cnt[8][256];
    __shared__ int ex[8][256];
    __shared__ int tot[8];
    __shared__ int segstart[8];
    __shared__ int sh_is64;

    const int b = blockIdx.x;
    const int tid = threadIdx.x;

    if (tid == 0) {
        int f = 1;
        #pragma unroll
        for (int k = 0; k < 32; k++)
            if (lab32[2 * k + 1] != 0) { f = 0; break; }
        sh_is64 = f;
    }
    __syncthreads();
    const int is64 = sh_is64;
    const int labbase = b * LM1;

    int mylab[16];
    int lh[8] = {0, 0, 0, 0, 0, 0, 0, 0};
    #pragma unroll
    for (int k = 0; k < 16; k++) {
        int i = tid * 16 + k;
        int l = -1;
        if (i < LM1) {
            int gi = labbase + i;
            l = lab32[is64 ? (2 * gi) : gi];
            lh[l]++;
        }
        mylab[k] = l;
    }
    #pragma unroll
    for (int l = 0; l < 8; l++) cnt[l][tid] = lh[l];
    __syncthreads();

    {
        int w = tid >> 5, lane = tid & 31;
        int carry = 0;
        for (int c = 0; c < 8; c++) {
            int t = c * 32 + lane;
            int v = cnt[w][t];
            int x = v;
            #pragma unroll
            for (int o = 1; o < 32; o <<= 1) {
                int y = __shfl_up_sync(0xffffffffu, x, o);
                if (lane >= o) x += y;
            }
            ex[w][t] = carry + x - v;
            carry += __shfl_sync(0xffffffffu, x, 31);
        }
        if (lane == 0) tot[w] = carry;
    }
    __syncthreads();

    if (tid == 0) {
        int s = 0;
        int nb = 0;
        #pragma unroll
        for (int l = 0; l < 8; l++) {
            segstart[l] = s;
            int e = s + tot[l];
            int kb = s & ~(BN - 1);
            int ke = min((e + BN - 1) & ~(BN - 1), LSEQ);
            for (int q0 = s; q0 < e; q0 += BM) {
                g_btab[b * MAXBLK + nb] = make_int4(q0, e, kb, ke);
                nb++;
            }
            s = e;
        }
        g_nblk[b] = nb;
        g_perm[b * LSEQ + LM1] = LM1;
        g_slab[b * LSEQ + LM1] = -2;
    }
    __syncthreads();

    int run[8] = {0, 0, 0, 0, 0, 0, 0, 0};
    #pragma unroll
    for (int k = 0; k < 16; k++) {
        int l = mylab[k];
        if (l >= 0) {
            int pos = segstart[l] + ex[l][tid] + run[l]++;
            int i = tid * 16 + k;
            g_perm[b * LSEQ + pos] = i;
            g_slab[b * LSEQ + pos] = l;
        }
    }
}

// ---------------------------------------------------------------------------
// Kernel B: gather K/V rows into sorted order (float4 granularity).
// ---------------------------------------------------------------------------
__global__ void gather_kernel(const float* __restrict__ K,
                              const float* __restrict__ V)
{
    int idx = blockIdx.x * blockDim.x + threadIdx.x;
    int r = idx >> 4;
    int c = idx & 15;
    int b = r >> 12;
    int src = g_perm[r];
    long long so = ((long long)(b << 12) + src) * 16 + c;
    ((float4*)g_Ks)[r * 16 + c] = ((const float4*)K)[so];
    ((float4*)g_Vs)[r * 16 + c] = ((const float4*)V)[so];
}

// ---------------------------------------------------------------------------
// Kernel C: main kernel, 256 threads.
//   slot <  nblk          : block-sparse flash attention (4x4 reg tiles)
//   nblk <= slot < nblk+16: one time-query split-softmax chunk (256 keys)
// ---------------------------------------------------------------------------
__global__ __launch_bounds__(NTHREADS, 2)
void clustered_attn_kernel(const float* __restrict__ Q,
                           const float* __restrict__ K,
                           const float* __restrict__ V,
                           float* __restrict__ Out)
{
    extern __shared__ float sm[];

    const int b    = blockIdx.y;
    const int slot = blockIdx.x;
    const int tid  = threadIdx.x;
    const int nblk = g_nblk[b];
    const long long bbase = (long long)b * LSEQ;
    const float scale = 0.125f;

    // ===================== time-query chunk path =====================
    if (slot >= nblk) {
        const int c = slot - nblk;
        if (c >= TQ_NCH) return;

        float* q    = sm;             // [64]
        float* p    = sm + 64;        // [256]
        float* red  = sm + 320;       // [16]
        float* vacc = sm + 336;       // [4][64]

        if (tid < HD) q[tid] = Q[(bbase + LM1) * HD + tid];
        __syncthreads();

        const int j = c * TQ_CHUNKS + tid;
        const float* kr = K + (bbase + j) * HD;
        float dot = 0.0f;
        #pragma unroll
        for (int d = 0; d < HD; d += 4) {
            float4 k4 = *reinterpret_cast<const float4*>(kr + d);
            dot += q[d] * k4.x + q[d + 1] * k4.y + q[d + 2] * k4.z + q[d + 3] * k4.w;
        }
        dot *= scale;

        float m = dot;
        #pragma unroll
        for (int o = 16; o >= 1; o >>= 1)
            m = fmaxf(m, __shfl_xor_sync(0xffffffffu, m, o));
        if ((tid & 31) == 0) red[tid >> 5] = m;
        __syncthreads();
        m = red[0];
        #pragma unroll
        for (int w = 1; w < 8; w++) m = fmaxf(m, red[w]);

        float pv = __expf(dot - m);
        p[tid] = pv;

        float s = pv;
        #pragma unroll
        for (int o = 16; o >= 1; o >>= 1)
            s += __shfl_xor_sync(0xffffffffu, s, o);
        if ((tid & 31) == 0) red[8 + (tid >> 5)] = s;
        __syncthreads();
        s = red[8];
        #pragma unroll
        for (int w = 1; w < 8; w++) s += red[8 + w];

        const int d = tid & 63, h = tid >> 6;     // h in 0..3
        float a = 0.0f;
        #pragma unroll 8
        for (int jj = h * 64; jj < h * 64 + 64; jj++)
            a += p[jj] * V[(bbase + c * TQ_CHUNKS + jj) * HD + d];
        vacc[h * HD + d] = a;
        __syncthreads();

        float* out = g_tq + (b * TQ_NCH + c) * (HD + 2);
        if (tid < HD)
            out[tid] = vacc[tid] + vacc[HD + tid] + vacc[2 * HD + tid] + vacc[3 * HD + tid];
        else if (tid == HD) { out[HD] = m; out[HD + 1] = s; }
        return;
    }

    // ===================== attention path (round-5 proven config) ==========
    float* Qt = sm;                       // [HD][PAD]  Qt[d*PAD + m]
    float* Kt = Qt + HD * PAD;            // [HD][PAD]
    float* Pt = Kt + HD * PAD;            // [BN][PAD]
    float* Vs = Pt + BN * PAD;            // [BN][HD]
    int*   klabs = (int*)(Vs + BN * HD);  // [BN]
    float* kt = (float*)(klabs + BN);     // [HD] time key
    float* vt = kt + HD;                  // [HD] time value

    const int4 blk = g_btab[b * MAXBLK + slot];
    const int q0 = blk.x, qe = blk.y, kb = blk.z, ke = blk.w;

    const int tx = tid & 15;
    const int ty = tid >> 4;
    const int* perm = g_perm + b * LSEQ;
    const int* slab = g_slab + b * LSEQ;

    const float* Kb = g_Ks + b * LSEQ * HD;
    const float* Vb = g_Vs + b * LSEQ * HD;

    // ---- Q tile (transposed) directly from original Q via perm:
    // 4 threads per row, each moves 4 float4 (16 floats).
    {
        int r = tid >> 2, h = tid & 3;
        int rr = min(q0 + r, LM1);
        int src = perm[rr];
        const float4* qrow = reinterpret_cast<const float4*>(Q + (bbase + src) * HD) + h * 4;
        #pragma unroll
        for (int k2 = 0; k2 < 4; k2++) {
            float4 v4 = qrow[k2];
            int d = h * 16 + k2 * 4;
            Qt[(d + 0) * PAD + r] = v4.x;
            Qt[(d + 1) * PAD + r] = v4.y;
            Qt[(d + 2) * PAD + r] = v4.z;
            Qt[(d + 3) * PAD + r] = v4.w;
        }
    }
    if (tid < HD) kt[tid] = Kb[LM1 * HD + tid];
    else if (tid < 2 * HD) vt[tid - HD] = Vb[LM1 * HD + (tid - HD)];

    int qlab[4];
    #pragma unroll
    for (int i = 0; i < 4; i++) {
        int r = q0 + ty * 4 + i;
        qlab[i] = (r < qe) ? slab[r] : -3;   // -3 matches nothing
    }

    float mrow[4], lrow[4], acc[4][4];
    #pragma unroll
    for (int i = 0; i < 4; i++) {
        mrow[i] = -INFINITY;
        lrow[i] = 0.0f;
        #pragma unroll
        for (int j = 0; j < 4; j++) acc[i][j] = 0.0f;
    }

    for (int n0 = kb; n0 < ke; n0 += BN) {
        __syncthreads();

        #pragma unroll
        for (int idx = tid; idx < BN * HD; idx += NTHREADS) {
            int n = idx >> 6, d = idx & 63;
            Kt[d * PAD + n] = Kb[(n0 + n) * HD + d];
            Vs[n * HD + d]  = Vb[(n0 + n) * HD + d];
        }
        if (tid < BN) klabs[tid] = slab[n0 + tid];
        __syncthreads();

        float s[4][4];
        #pragma unroll
        for (int i = 0; i < 4; i++)
            #pragma unroll
            for (int j = 0; j < 4; j++) s[i][j] = 0.0f;

        #pragma unroll 8
        for (int d = 0; d < HD; d++) {
            float a[4], bb[4];
            #pragma unroll
            for (int i = 0; i < 4; i++) a[i]  = Qt[d * PAD + 4 * ty + i];
            #pragma unroll
            for (int j = 0; j < 4; j++) bb[j] = Kt[d * PAD + 4 * tx + j];
            #pragma unroll
            for (int i = 0; i < 4; i++)
                #pragma unroll
                for (int j = 0; j < 4; j++) s[i][j] += a[i] * bb[j];
        }

        int klj[4];
        #pragma unroll
        for (int j = 0; j < 4; j++) klj[j] = klabs[4 * tx + j];

        #pragma unroll
        for (int i = 0; i < 4; i++)
            #pragma unroll
            for (int j = 0; j < 4; j++)
                s[i][j] = (qlab[i] == klj[j]) ? s[i][j] * scale : -INFINITY;

        #pragma unroll
        for (int i = 0; i < 4; i++) {
            float tm = fmaxf(fmaxf(s[i][0], s[i][1]), fmaxf(s[i][2], s[i][3]));
            #pragma unroll
            for (int o = 8; o >= 1; o >>= 1)
                tm = fmaxf(tm, __shfl_xor_sync(0xffffffffu, tm, o));

            float newm = fmaxf(mrow[i], tm);
            float mref = (newm == -INFINITY) ? 0.0f : newm;
            float f = __expf(mrow[i] - mref);

            float rs = 0.0f;
            #pragma unroll
            for (int j = 0; j < 4; j++) {
                float p = __expf(s[i][j] - mref);
                s[i][j] = p;
                rs += p;
            }
            #pragma unroll
            for (int o = 8; o >= 1; o >>= 1)
                rs += __shfl_xor_sync(0xffffffffu, rs, o);

            lrow[i] = lrow[i] * f + rs;
            mrow[i] = newm;
            #pragma unroll
            for (int j = 0; j < 4; j++) acc[i][j] *= f;
        }

        #pragma unroll
        for (int i = 0; i < 4; i++)
            #pragma unroll
            for (int j = 0; j < 4; j++)
                Pt[(4 * tx + j) * PAD + (4 * ty + i)] = s[i][j];
        __syncthreads();

        #pragma unroll 8
        for (int n = 0; n < BN; n++) {
            float a[4], bb[4];
            #pragma unroll
            for (int i = 0; i < 4; i++) a[i]  = Pt[n * PAD + 4 * ty + i];
            #pragma unroll
            for (int j = 0; j < 4; j++) bb[j] = Vs[n * HD + 4 * tx + j];
            #pragma unroll
            for (int i = 0; i < 4; i++)
                #pragma unroll
                for (int j = 0; j < 4; j++) acc[i][j] += a[i] * bb[j];
        }
    }

    // ---- time key column
    #pragma unroll
    for (int i = 0; i < 4; i++) {
        float part = 0.0f;
        #pragma unroll
        for (int jj = 0; jj < 4; jj++)
            part += Qt[(4 * tx + jj) * PAD + (4 * ty + i)] * kt[4 * tx + jj];
        #pragma unroll
        for (int o = 8; o >= 1; o >>= 1)
            part += __shfl_xor_sync(0xffffffffu, part, o);
        float st = part * scale;

        float newm = fmaxf(mrow[i], st);
        float f = __expf(mrow[i] - newm);
        float p = __expf(st - newm);
        lrow[i] = lrow[i] * f + p;
        mrow[i] = newm;
        #pragma unroll
        for (int j = 0; j < 4; j++)
            acc[i][j] = acc[i][j] * f + p * vt[4 * tx + j];
    }

    // ---- epilogue: normalize + scatter
    #pragma unroll
    for (int i = 0; i < 4; i++) {
        int r = q0 + 4 * ty + i;
        if (r < qe) {
            float inv = 1.0f / lrow[i];
            int orig = perm[r];
            float4 o4;
            o4.x = acc[i][0] * inv;
            o4.y = acc[i][1] * inv;
            o4.z = acc[i][2] * inv;
            o4.w = acc[i][3] * inv;
            *reinterpret_cast<float4*>(&Out[(bbase + orig) * HD + 4 * tx]) = o4;
        }
    }
}

// ---------------------------------------------------------------------------
// Kernel D: combine time-query partials. Grid = B, 64 threads.
// ---------------------------------------------------------------------------
__global__ void timeq_combine(float* __restrict__ Out)
{
    const int b = blockIdx.x;
    const int tid = threadIdx.x;
    const float* part = g_tq + b * TQ_NCH * (HD + 2);

    float M = -INFINITY;
    #pragma unroll
    for (int c = 0; c < TQ_NCH; c++)
        M = fmaxf(M, part[c * (HD + 2) + HD]);

    float stot = 0.0f, a = 0.0f;
    #pragma unroll
    for (int c = 0; c < TQ_NCH; c++) {
        float f = __expf(part[c * (HD + 2) + HD] - M);
        stot += part[c * (HD + 2) + HD + 1] * f;
        a    += part[c * (HD + 2) + tid] * f;
    }
    Out[((long long)b * LSEQ + LM1) * HD + tid] = a / stot;
}

// ---------------------------------------------------------------------------
extern "C" void kernel_launch(void* const* d_in, const int* in_sizes, int n_in,
                              void* d_out, int out_size)
{
    const float* Q = (const float*)d_in[0];
    const float* K = (const float*)d_in[1];
    const float* V = (const float*)d_in[2];
    const int* lab = (const int*)d_in[3];
    float* Out = (float*)d_out;

    const int B = in_sizes[0] / (LSEQ * HD);

    sort_kernel<<<B, 256>>>(lab);
    gather_kernel<<<B * 256, 256>>>(K, V);

    const int smem_bytes = (HD * PAD * 2 + BN * PAD + BN * HD + 2 * HD) * (int)sizeof(float)
                           + BN * (int)sizeof(int);
    cudaFuncSetAttribute(clustered_attn_kernel,
                         cudaFuncAttributeMaxDynamicSharedMemorySize, smem_bytes);
    dim3 grid(GRIDX, B);
    clustered_attn_kernel<<<grid, NTHREADS, smem_bytes>>>(Q, K, V, Out);

    timeq_combine<<<B, HD>>>(Out);
}